// round 1
// baseline (speedup 1.0000x reference)
#include <cuda_runtime.h>

#define B_ 4
#define C_ 256
#define N_ 4096
#define CI_ 32
#define QKV_PITCH 320

// 20 MB scratch for fused [V | Q | K] projection, row-major per position:
// g_qkv[b][n][0:256]=V row, [256:288]=Q row, [288:320]=K row
__device__ float g_qkv[(size_t)B_ * N_ * QKV_PITCH];

// ---------------------------------------------------------------------------
// Kernel 1: QKV projection.  out[b,n,j] = sum_c W[j,c] * x[b,c,n]
// GEMM per batch: M=4096 (n) x N=384 (j padded, 320 real) x K=256 (c)
// ---------------------------------------------------------------------------
__global__ __launch_bounds__(256) void qkv_proj_kernel(
    const float* __restrict__ x, const float* __restrict__ wv,
    const float* __restrict__ wq, const float* __restrict__ wk)
{
    const int b  = blockIdx.z;
    const int nb = blockIdx.x * 128;   // n tile base
    const int j0 = blockIdx.y * 128;   // j tile base (0,128,256)
    const int tid = threadIdx.x;
    const int tyy = tid >> 4;          // 0..15 (row group)
    const int txx = tid & 15;          // 0..15 (col group)

    __shared__ float xs[16][128];      // x^T tile: xs[k][n]
    __shared__ float ws[16][132];      // W tile:  ws[k][j] (padded pitch)

    float acc[8][8];
#pragma unroll
    for (int i = 0; i < 8; i++)
#pragma unroll
        for (int j = 0; j < 8; j++) acc[i][j] = 0.f;

    const float* xb = x + (size_t)b * C_ * N_;

    for (int c0 = 0; c0 < C_; c0 += 16) {
        // load x tile (coalesced float4 along n)
#pragma unroll
        for (int w = 0; w < 2; w++) {
            int f4 = tid + w * 256;            // 0..511
            int k  = f4 >> 5, n4 = f4 & 31;
            float4 v = *(const float4*)(xb + (size_t)(c0 + k) * N_ + nb + n4 * 4);
            *(float4*)(&xs[k][n4 * 4]) = v;
        }
        // load W tile (stacked wv/wq/wk, zero-pad j>=320)
#pragma unroll
        for (int it = 0; it < 8; it++) {
            int jl = (tid >> 4) + it * 16;     // 0..127
            int k  = tid & 15;
            int j  = j0 + jl;
            int c  = c0 + k;
            float val = 0.f;
            if (j < 256)      val = wv[j * C_ + c];
            else if (j < 288) val = wq[(j - 256) * C_ + c];
            else if (j < 320) val = wk[(j - 288) * C_ + c];
            ws[k][jl] = val;
        }
        __syncthreads();
#pragma unroll
        for (int k = 0; k < 16; k++) {
            float a[8], bb[8];
            *(float4*)&a[0]  = *(const float4*)&xs[k][tyy * 4];
            *(float4*)&a[4]  = *(const float4*)&xs[k][64 + tyy * 4];
            *(float4*)&bb[0] = *(const float4*)&ws[k][txx * 4];
            *(float4*)&bb[4] = *(const float4*)&ws[k][64 + txx * 4];
#pragma unroll
            for (int i = 0; i < 8; i++)
#pragma unroll
                for (int j = 0; j < 8; j++)
                    acc[i][j] = fmaf(a[i], bb[j], acc[i][j]);
        }
        __syncthreads();
    }

    float* qout = g_qkv + (size_t)b * N_ * QKV_PITCH;
#pragma unroll
    for (int i = 0; i < 8; i++) {
        int row = nb + ((i < 4) ? (tyy * 4 + i) : (64 + tyy * 4 + i - 4));
#pragma unroll
        for (int cb = 0; cb < 2; cb++) {
            int j = j0 + cb * 64 + txx * 4;
            if (j < QKV_PITCH) {
                float4 v = make_float4(acc[i][cb * 4 + 0], acc[i][cb * 4 + 1],
                                       acc[i][cb * 4 + 2], acc[i][cb * 4 + 3]);
                *(float4*)(qout + (size_t)row * QKV_PITCH + j) = v;
            }
        }
    }
}

// ---------------------------------------------------------------------------
// Kernel 2: fused flash attention (distance-divided scores, online softmax,
// P@V) + BatchNorm + ReLU + residual epilogue.
// One CTA = one batch b, one 64-row query tile. 256 threads.
// Thread (ty=warp 0..7, tx=lane): rows r = ty*8+i (i<8),
// cols c in {tx*4..tx*4+3} U {128+tx*4..+3}.  acc: 8x8 fp32 regs.
// ---------------------------------------------------------------------------
#define TQ 64
#define TM 64

// shared memory layout (in floats)
#define QS_OFF 0                      // Qs[64][32]
#define KS_OFF 2048                   // Ks[64][36]   (padded)
#define VS_OFF (2048 + 2304)          // Vs[64][260]  (padded; reused as sacc)
#define PT_OFF (VS_OFF + 16640)       // Pt[64][72]   (P transposed [m][r])
#define LS_OFF (PT_OFF + 4608)        // ls[64]
#define SMEM_FLOATS (LS_OFF + 64)
#define SMEM_BYTES (SMEM_FLOATS * 4)  // 102,656 B -> 2 CTAs/SM

__global__ __launch_bounds__(256, 2) void attn_kernel(
    const float* __restrict__ x, const float* __restrict__ gamma,
    const float* __restrict__ beta, const float* __restrict__ mean,
    const float* __restrict__ var, float* __restrict__ out)
{
    extern __shared__ float sm[];
    float* Qs = sm + QS_OFF;
    float* Ks = sm + KS_OFF;
    float* Vs = sm + VS_OFF;
    float* Pt = sm + PT_OFF;
    float* ls = sm + LS_OFF;

    const int b   = blockIdx.y;
    const int qb  = blockIdx.x * TQ;
    const int tid = threadIdx.x;
    const int ty  = tid >> 5;   // warp id 0..7
    const int tx  = tid & 31;   // lane
    const float* qkv = g_qkv + (size_t)b * N_ * QKV_PITCH;

    // load Q tile [64][32]
#pragma unroll
    for (int w = 0; w < 2; w++) {
        int f4 = tid + w * 256;
        int row = f4 >> 3, c4 = f4 & 7;
        float4 v = *(const float4*)(qkv + (size_t)(qb + row) * QKV_PITCH + 256 + c4 * 4);
        *(float4*)(Qs + row * 32 + c4 * 4) = v;
    }

    float acc[8][8];
#pragma unroll
    for (int i = 0; i < 8; i++)
#pragma unroll
        for (int j = 0; j < 8; j++) acc[i][j] = 0.f;

    float mrow[8], lrow[8];
#pragma unroll
    for (int i = 0; i < 8; i++) { mrow[i] = -1e30f; lrow[i] = 0.f; }

    for (int kb = 0; kb < N_; kb += TM) {
        __syncthreads();   // previous P@V done reading Ks/Vs/Pt
        // load K tile [64][32] -> Ks pitch 36
#pragma unroll
        for (int w = 0; w < 2; w++) {
            int f4 = tid + w * 256;
            int row = f4 >> 3, c4 = f4 & 7;
            float4 v = *(const float4*)(qkv + (size_t)(kb + row) * QKV_PITCH + 288 + c4 * 4);
            *(float4*)(Ks + row * 36 + c4 * 4) = v;
        }
        // load V tile [64][256] -> Vs pitch 260
#pragma unroll
        for (int w = 0; w < 16; w++) {
            int f4 = tid + w * 256;
            int row = f4 >> 6, c4 = f4 & 63;
            float4 v = *(const float4*)(qkv + (size_t)(kb + row) * QKV_PITCH + c4 * 4);
            *(float4*)(Vs + row * 260 + c4 * 4) = v;
        }
        __syncthreads();

        // ---- S = Q K^T for this thread's 8 rows x 2 key cols (m=tx, tx+32)
        float s0[8], s1[8];
#pragma unroll
        for (int i = 0; i < 8; i++) { s0[i] = 0.f; s1[i] = 0.f; }
#pragma unroll
        for (int c4 = 0; c4 < 8; c4++) {
            float4 k0 = *(const float4*)(Ks + tx * 36 + c4 * 4);
            float4 k1 = *(const float4*)(Ks + (tx + 32) * 36 + c4 * 4);
#pragma unroll
            for (int i = 0; i < 8; i++) {
                float4 q = *(const float4*)(Qs + (ty * 8 + i) * 32 + c4 * 4);
                s0[i] = fmaf(q.x, k0.x, fmaf(q.y, k0.y, fmaf(q.z, k0.z, fmaf(q.w, k0.w, s0[i]))));
                s1[i] = fmaf(q.x, k1.x, fmaf(q.y, k1.y, fmaf(q.z, k1.z, fmaf(q.w, k1.w, s1[i]))));
            }
        }

        // ---- divide by distance, online softmax, write P^T
        const int m0 = kb + tx, m1 = kb + tx + 32;
        const int m0y = m0 >> 6, m0x = m0 & 63;
        const int m1y = m1 >> 6, m1x = m1 & 63;
#pragma unroll
        for (int i = 0; i < 8; i++) {
            const int r  = qb + ty * 8 + i;
            const int ry = r >> 6, rx = r & 63;
            int dy0 = ry - m0y, dx0 = rx - m0x;
            int dy1 = ry - m1y, dx1 = rx - m1x;
            float d0 = sqrtf((float)(dy0 * dy0 + dx0 * dx0)) + 1.0f;
            float d1 = sqrtf((float)(dy1 * dy1 + dx1 * dx1)) + 1.0f;
            s0[i] /= d0;
            s1[i] /= d1;

            float ml = fmaxf(s0[i], s1[i]);
#pragma unroll
            for (int off = 16; off; off >>= 1)
                ml = fmaxf(ml, __shfl_xor_sync(0xffffffffu, ml, off));
            float mnew = fmaxf(mrow[i], ml);
            float p0 = __expf(s0[i] - mnew);
            float p1 = __expf(s1[i] - mnew);
            float psum = p0 + p1;
#pragma unroll
            for (int off = 16; off; off >>= 1)
                psum += __shfl_xor_sync(0xffffffffu, psum, off);
            float scale = __expf(mrow[i] - mnew);
            lrow[i] = lrow[i] * scale + psum;
            mrow[i] = mnew;
            if (scale != 1.0f) {
#pragma unroll
                for (int j = 0; j < 8; j++) acc[i][j] *= scale;
            }
            Pt[tx * 72 + ty * 8 + i]        = p0;
            Pt[(tx + 32) * 72 + ty * 8 + i] = p1;
        }
        __syncthreads();

        // ---- P @ V : per m, 4x LDS.128 feeding 64 FFMA
#pragma unroll 2
        for (int m = 0; m < TM; m++) {
            float4 pa = *(const float4*)(Pt + m * 72 + ty * 8);
            float4 pb = *(const float4*)(Pt + m * 72 + ty * 8 + 4);
            float4 va = *(const float4*)(Vs + m * 260 + tx * 4);
            float4 vb = *(const float4*)(Vs + m * 260 + 128 + tx * 4);
            float p[8]  = {pa.x, pa.y, pa.z, pa.w, pb.x, pb.y, pb.z, pb.w};
            float vv[8] = {va.x, va.y, va.z, va.w, vb.x, vb.y, vb.z, vb.w};
#pragma unroll
            for (int i = 0; i < 8; i++)
#pragma unroll
                for (int j = 0; j < 8; j++)
                    acc[i][j] = fmaf(p[i], vv[j], acc[i][j]);
        }
    }

    // ---- epilogue: transpose through smem, BN + ReLU + residual, coalesced out
    __syncthreads();
#pragma unroll
    for (int i = 0; i < 8; i++) {
        int r = ty * 8 + i;
        *(float4*)(Vs + r * 260 + tx * 4)       = make_float4(acc[i][0], acc[i][1], acc[i][2], acc[i][3]);
        *(float4*)(Vs + r * 260 + 128 + tx * 4) = make_float4(acc[i][4], acc[i][5], acc[i][6], acc[i][7]);
        if (tx == 0) ls[r] = lrow[i];
    }
    __syncthreads();

    const int nl = tid & 63;          // local row (n within tile)
    const int cg = tid >> 6;          // channel group 0..3
    const float rl = 1.0f / ls[nl];
    const size_t obase = (size_t)b * C_ * N_ + qb + nl;
    for (int c = cg; c < C_; c += 4) {
        float inv = gamma[c] * rsqrtf(var[c] + 1e-5f);
        float add = fmaf(-mean[c], inv, beta[c]);
        float y   = Vs[nl * 260 + c] * rl;
        float val = fmaf(y, inv, add);
        val = fmaxf(val, 0.0f) + x[obase + (size_t)c * N_];
        out[obase + (size_t)c * N_] = val;
    }
}

// ---------------------------------------------------------------------------
extern "C" void kernel_launch(void* const* d_in, const int* in_sizes, int n_in,
                              void* d_out, int out_size)
{
    (void)in_sizes; (void)n_in; (void)out_size;
    const float* x     = (const float*)d_in[0];
    const float* wv    = (const float*)d_in[1];
    const float* wq    = (const float*)d_in[2];
    const float* wk    = (const float*)d_in[3];
    const float* gamma = (const float*)d_in[4];
    const float* beta  = (const float*)d_in[5];
    const float* mean  = (const float*)d_in[6];
    const float* var   = (const float*)d_in[7];
    // d_in[8] = distance: recomputed analytically in-kernel, not read.
    float* out = (float*)d_out;

    qkv_proj_kernel<<<dim3(N_ / 128, 3, B_), 256>>>(x, wv, wq, wk);

    cudaFuncSetAttribute(attn_kernel, cudaFuncAttributeMaxDynamicSharedMemorySize, SMEM_BYTES);
    attn_kernel<<<dim3(N_ / TQ, B_), 256, SMEM_BYTES>>>(x, gamma, beta, mean, var, out);
}